// round 17
// baseline (speedup 1.0000x reference)
#include <cuda_runtime.h>
#include <cstdint>

#define Bb   2
#define Nn   2048
#define Cc   512
#define Hh   8
#define HD   64
#define BH   16
#define KTOP 1024
#define SCALEF 0.125f
#define JSPLIT 4
#define JLEN  (Nn / JSPLIT)     // 512

typedef unsigned long long ull;

// ---------------- scratch ----------------
__device__ float g_Qh[BH * Nn * HD];
__device__ float g_Kh[BH * Nn * HD];
__device__ float g_Vh[BH * Nn * HD];
__device__ float g_attn[(size_t)BH * Nn * Nn];
__device__ float g_attnT[(size_t)BH * Nn * Nn];
__device__ float g_rth[BH * Nn];
__device__ float g_cth[BH * Nn];
__device__ float g_rmax[BH * Nn];
__device__ float g_O[BH * Nn * HD];
__device__ float g_Opart[(size_t)JSPLIT * BH * Nn * HD];   // 32MB
__device__ float g_dpart[JSPLIT * BH * Nn];

// ---------------- tf32 / f32x2 helpers ----------------
__device__ __forceinline__ unsigned tf32_rna(float x) {
    unsigned u; asm("cvt.rna.tf32.f32 %0, %1;" : "=r"(u) : "f"(x)); return u;
}
__device__ __forceinline__ void split_tf32(float x, unsigned& hi, unsigned& lo) {
    hi = tf32_rna(x);
    float hf = __uint_as_float(hi);
    lo = tf32_rna(x - hf);
}
__device__ __forceinline__ void mma_tf32(float* c, const unsigned* a, const unsigned* b) {
    asm("mma.sync.aligned.m16n8k8.row.col.f32.tf32.tf32.f32 "
        "{%0,%1,%2,%3},{%4,%5,%6,%7},{%8,%9},{%0,%1,%2,%3};"
        : "+f"(c[0]), "+f"(c[1]), "+f"(c[2]), "+f"(c[3])
        : "r"(a[0]), "r"(a[1]), "r"(a[2]), "r"(a[3]), "r"(b[0]), "r"(b[1]));
}
__device__ __forceinline__ ull pack2(float lo, float hi) {
    ull r; asm("mov.b64 %0,{%1,%2};" : "=l"(r) : "f"(lo), "f"(hi)); return r;
}
__device__ __forceinline__ void ffma2(ull& d, ull a, ull b) {
    asm("fma.rn.f32x2 %0,%1,%2,%3;" : "=l"(d) : "l"(a), "l"(b), "l"(d));
}
__device__ __forceinline__ float2 unpack2(ull v) {
    float2 f; asm("mov.b64 {%0,%1},%2;" : "=f"(f.x), "=f"(f.y) : "l"(v)); return f;
}

// ---------------------------------------------------------------------------
// Kernel 1: ALL THREE projections in one launch (grid.z = which).  (R10 exact)
// ---------------------------------------------------------------------------
__global__ __launch_bounds__(128) void proj_kernel(const float* __restrict__ q,
                                                   const float* __restrict__ k_v,
                                                   const float* __restrict__ Wq,
                                                   const float* __restrict__ Wk,
                                                   const float* __restrict__ Wv) {
    __shared__ float As[128][33];
    __shared__ float Bs[64][33];
    int which = blockIdx.z;
    const float* X = (which == 0) ? q : k_v;
    const float* W = (which == 0) ? Wq : ((which == 1) ? Wk : Wv);
    int tid = threadIdx.x;
    int tx = tid & 7, ty = tid >> 3;
    int m0 = blockIdx.y * 128, n0 = blockIdx.x * 64;
    float acc[8][8] = {};
    for (int k0 = 0; k0 < Cc; k0 += 32) {
#pragma unroll
        for (int l = tid; l < 1024; l += 128) {
            int m = l >> 3, c = (l & 7) * 4;
            float4 v = *(const float4*)&X[(size_t)(m0 + m) * Cc + k0 + c];
            As[m][c] = v.x; As[m][c + 1] = v.y; As[m][c + 2] = v.z; As[m][c + 3] = v.w;
        }
#pragma unroll
        for (int l = tid; l < 512; l += 128) {
            int n = l >> 3, c = (l & 7) * 4;
            float4 v = *(const float4*)&W[(size_t)(n0 + n) * Cc + k0 + c];
            Bs[n][c] = v.x; Bs[n][c + 1] = v.y; Bs[n][c + 2] = v.z; Bs[n][c + 3] = v.w;
        }
        __syncthreads();
#pragma unroll
        for (int kk = 0; kk < 32; kk++) {
            float a[8], b[8];
#pragma unroll
            for (int i = 0; i < 8; i++) a[i] = As[8 * ty + i][kk];
#pragma unroll
            for (int j = 0; j < 8; j++) b[j] = Bs[8 * tx + j][kk];
#pragma unroll
            for (int i = 0; i < 8; i++)
#pragma unroll
                for (int j = 0; j < 8; j++) acc[i][j] += a[i] * b[j];
        }
        __syncthreads();
    }
    float* out = (which == 0) ? g_Qh : ((which == 1) ? g_Kh : g_Vh);
#pragma unroll
    for (int i = 0; i < 8; i++) {
        int m = m0 + 8 * ty + i;
        int bb = m >> 11, nl = m & (Nn - 1);
#pragma unroll
        for (int j = 0; j < 8; j++) {
            int n = n0 + 8 * tx + j;
            int h = n >> 6, d = n & 63;
            out[(((size_t)(bb * Hh + h)) * Nn + nl) * HD + d] = acc[i][j];
        }
    }
}

// ---------------------------------------------------------------------------
// Kernel 2: attn = scale * Q K^T via 3xTF32 mma.sync, M=128 x N=64.  (R16 exact)
// ---------------------------------------------------------------------------
__global__ __launch_bounds__(256) void qk_tc_kernel() {
    __shared__ float sm[128 * 36 + 64 * 36];     // 27.6KB
    float (*Qs)[36] = (float(*)[36])sm;
    float (*Ks)[36] = (float(*)[36])(sm + 128 * 36);
    float (*Ts)[68] = (float(*)[68])sm;          // 64x68 overlay

    int tid = threadIdx.x;
    int wid = tid >> 5, lane = tid & 31;
    int g = lane >> 2, t = lane & 3;
    int wm = wid & 3, wn = wid >> 2;
    int bh = blockIdx.z;
    int i0 = blockIdx.y * 128, j0 = blockIdx.x * 64;
    const float* Q = g_Qh + (size_t)bh * Nn * HD;
    const float* K = g_Kh + (size_t)bh * Nn * HD;

    float acc[2][4][4] = {};
#pragma unroll
    for (int kc = 0; kc < HD; kc += 32) {
#pragma unroll
        for (int p = 0; p < 4; p++) {
            int idx = p * 256 + tid;
            int m = idx >> 3, c = (idx & 7) * 4;
            float4 v = *(const float4*)&Q[(size_t)(i0 + m) * HD + kc + c];
            *(float4*)&Qs[m][c] = v;
        }
#pragma unroll
        for (int p = 0; p < 2; p++) {
            int idx = p * 256 + tid;
            int n = idx >> 3, c = (idx & 7) * 4;
            float4 v = *(const float4*)&K[(size_t)(j0 + n) * HD + kc + c];
            *(float4*)&Ks[n][c] = v;
        }
        __syncthreads();
#pragma unroll
        for (int ks = 0; ks < 4; ks++) {
            int k0 = ks * 8;
            unsigned ahi[2][4], alo[2][4], bhi[4][2], blo[4][2];
#pragma unroll
            for (int mt = 0; mt < 2; mt++) {
                int rb = 32 * wm + 16 * mt;
                float x0 = Qs[rb + g][k0 + t];
                float x1 = Qs[rb + g + 8][k0 + t];
                float x2 = Qs[rb + g][k0 + t + 4];
                float x3 = Qs[rb + g + 8][k0 + t + 4];
                split_tf32(x0, ahi[mt][0], alo[mt][0]);
                split_tf32(x1, ahi[mt][1], alo[mt][1]);
                split_tf32(x2, ahi[mt][2], alo[mt][2]);
                split_tf32(x3, ahi[mt][3], alo[mt][3]);
            }
#pragma unroll
            for (int nt = 0; nt < 4; nt++) {
                int nb = 32 * wn + 8 * nt;
                float y0 = Ks[nb + g][k0 + t];
                float y1 = Ks[nb + g][k0 + t + 4];
                split_tf32(y0, bhi[nt][0], blo[nt][0]);
                split_tf32(y1, bhi[nt][1], blo[nt][1]);
            }
#pragma unroll
            for (int mt = 0; mt < 2; mt++)
#pragma unroll
                for (int nt = 0; nt < 4; nt++) {
                    mma_tf32(acc[mt][nt], ahi[mt], blo[nt]);
                    mma_tf32(acc[mt][nt], alo[mt], bhi[nt]);
                    mma_tf32(acc[mt][nt], ahi[mt], bhi[nt]);
                }
        }
        __syncthreads();
    }

#pragma unroll
    for (int pass = 0; pass < 2; pass++) {
        if ((wm >> 1) == pass) {
#pragma unroll
            for (int mt = 0; mt < 2; mt++)
#pragma unroll
                for (int nt = 0; nt < 4; nt++) {
                    int r0 = 32 * (wm & 1) + 16 * mt + g;
                    int c0 = 32 * wn + 8 * nt + 2 * t;
                    Ts[r0][c0]         = acc[mt][nt][0] * SCALEF;
                    Ts[r0][c0 + 1]     = acc[mt][nt][1] * SCALEF;
                    Ts[r0 + 8][c0]     = acc[mt][nt][2] * SCALEF;
                    Ts[r0 + 8][c0 + 1] = acc[mt][nt][3] * SCALEF;
                }
        }
        __syncthreads();
        float* attn = g_attn + ((size_t)bh * Nn + i0 + 64 * pass) * Nn + j0;
#pragma unroll
        for (int p = 0; p < 4; p++) {
            int idx = p * 256 + tid;
            int r = idx >> 4, cq = (idx & 15) * 4;
            *(float4*)&attn[(size_t)r * Nn + cq] = *(const float4*)&Ts[r][cq];
        }
        float* attnT = g_attnT + ((size_t)bh * Nn + j0) * Nn + i0 + 64 * pass;
#pragma unroll
        for (int p = 0; p < 16; p++) {
            int idx = p * 256 + tid;
            int jl = idx >> 6, il = idx & 63;
            attnT[(size_t)jl * Nn + il] = Ts[il][jl];
        }
        __syncthreads();
    }
}

// ---------------------------------------------------------------------------
// Kernel 3: PAIRED radix select   (R13 exact)
// ---------------------------------------------------------------------------
__global__ __launch_bounds__(256) void select_kernel() {
    __shared__ unsigned hist[2][2][256];
    __shared__ unsigned S[2][257];
    __shared__ unsigned s_selbin[2];
    __shared__ unsigned s_maxu;
    int tid = threadIdx.x;
    int sel = tid >> 7;           // 0: attn row, 1: attnT row
    int st  = tid & 127;
    int copy = (st >> 6) & 1;
    int lane = tid & 31;
    size_t row = blockIdx.x;
    const float* src = (sel ? g_attnT : g_attn) + row * Nn;

    unsigned u[16];
    unsigned lmax = 0u;
#pragma unroll
    for (int q = 0; q < 4; q++) {
        float4 v = *(const float4*)&src[st * 16 + 4 * q];
        float vals[4] = {v.x, v.y, v.z, v.w};
#pragma unroll
        for (int r = 0; r < 4; r++) {
            unsigned b = __float_as_uint(vals[r]);
            unsigned k = b ^ ((unsigned)((int)b >> 31) | 0x80000000u);
            u[4 * q + r] = k;
            lmax = lmax > k ? lmax : k;
        }
    }
    if (tid == 0) s_maxu = 0u;

    unsigned prefix = 0u;
    int krem = KTOP;
#pragma unroll
    for (int pass = 0; pass < 4; pass++) {
        int shift = 24 - 8 * pass;
#pragma unroll
        for (int i = tid; i < 1024; i += 256) ((unsigned*)hist)[i] = 0u;
        __syncthreads();
        if (pass == 0 && sel == 0) atomicMax(&s_maxu, lmax);
        unsigned himask = (pass == 0) ? 0u : (0xFFFFFFFFu << (shift + 8));
#pragma unroll
        for (int r = 0; r < 16; r++)
            if ((u[r] & himask) == prefix)
                atomicAdd(&hist[sel][copy][(u[r] >> shift) & 255u], 1u);
        __syncthreads();
        int wid = tid >> 5;
        if (wid == 0 || wid == 4) {
            int s = wid >> 2;
            int base = lane * 8;
            unsigned c[8], loc[8];
#pragma unroll
            for (int j = 0; j < 8; j++)
                c[j] = hist[s][0][base + j] + hist[s][1][base + j];
            loc[7] = c[7];
#pragma unroll
            for (int j = 6; j >= 0; j--) loc[j] = c[j] + loc[j + 1];
            unsigned T = loc[0], incl = T;
#pragma unroll
            for (int off = 1; off < 32; off <<= 1) {
                unsigned v = __shfl_down_sync(0xFFFFFFFFu, incl, off);
                if (lane + off < 32) incl += v;
            }
            unsigned excl = incl - T;
#pragma unroll
            for (int j = 0; j < 8; j++) S[s][base + j] = excl + loc[j];
            if (lane == 0) S[s][256] = 0u;
        }
        __syncthreads();
#pragma unroll
        for (int q = 0; q < 2; q++) {
            int b = 2 * st + q;
            unsigned St = S[sel][b], St1 = S[sel][b + 1];
            if ((int)St >= krem && (int)St1 < krem) s_selbin[sel] = (unsigned)b;
        }
        __syncthreads();
        unsigned selb = s_selbin[sel];
        krem -= (int)S[sel][selb + 1];
        prefix |= selb << shift;
        __syncthreads();
    }
    if (st == 0) {
        unsigned b = (prefix & 0x80000000u) ? (prefix ^ 0x80000000u) : ~prefix;
        float thr = __uint_as_float(b);
        if (sel) {
            g_cth[row] = thr;
        } else {
            g_rth[row] = thr;
            unsigned um = s_maxu;
            unsigned bm = (um & 0x80000000u) ? (um ^ 0x80000000u) : ~um;
            g_rmax[row] = __uint_as_float(bm);
        }
    }
}

// ---------------------------------------------------------------------------
// Kernel 4: fused masked softmax + P@V, J-SPLIT partials.
// R15 structure; MMA loop upgraded to fma.rn.f32x2 (j-pairs contiguous in
// Vs -> ulonglong2 loads; a packed as (a,a)).  IEEE fma per lane, same
// per-element kk order -> outputs bit-identical to R15/R16.
// grid (Nn/128, JSPLIT, BH), block 128, 4 blocks/SM.
// ---------------------------------------------------------------------------
__global__ __launch_bounds__(128, 4) void spv_part_kernel() {
    __shared__ float Ps[128][33];
    __shared__ __align__(16) float Vs[32][68];
    __shared__ float s_rth[128], s_mx[128], s_den[128];
    int tid = threadIdx.x;
    int tx = tid & 7, ty = tid >> 3;
    int bh = blockIdx.z;
    int part = blockIdx.y;
    int js = part * JLEN;
    int i0 = blockIdx.x * 128;
    const float* V = g_Vh + (size_t)bh * Nn * HD;
    const float* A = g_attn + ((size_t)bh * Nn + i0) * Nn;
    const float* CT = g_cth + bh * Nn;
    s_rth[tid] = g_rth[bh * Nn + i0 + tid];
    s_mx[tid]  = g_rmax[bh * Nn + i0 + tid];
    s_den[tid] = 0.f;
    __syncthreads();
    float rthr[8], mr[8], dloc[8];
#pragma unroll
    for (int i = 0; i < 8; i++) {
        rthr[i] = s_rth[8 * ty + i];
        mr[i]   = s_mx[8 * ty + i];
        dloc[i] = 0.f;
    }
    ull acc2[8][4] = {};

    for (int j0 = js; j0 < js + JLEN; j0 += 32) {
        __syncthreads();
#pragma unroll
        for (int l = tid; l < 512; l += 128) {
            int jl = l >> 4, d = (l & 15) * 4;
            *(float4*)&Vs[jl][d] = *(const float4*)&V[(size_t)(j0 + jl) * HD + d];
        }
        float4 ct4 = *(const float4*)&CT[j0 + 4 * tx];
        float cthv[4] = {ct4.x, ct4.y, ct4.z, ct4.w};
#pragma unroll
        for (int i = 0; i < 8; i++) {
            float4 av4 = *(const float4*)&A[(size_t)(8 * ty + i) * Nn + j0 + 4 * tx];
            float av[4] = {av4.x, av4.y, av4.z, av4.w};
#pragma unroll
            for (int uu = 0; uu < 4; uu++) {
                float a = av[uu];
                float thr = fminf(rthr[i], cthv[uu]);
                float p = (a >= thr) ? __expf(a - mr[i]) : 0.f;
                dloc[i] += p;
                Ps[8 * ty + i][4 * tx + uu] = p;
            }
        }
        __syncthreads();
#pragma unroll
        for (int kk = 0; kk < 32; kk++) {
            ull aB[8];
#pragma unroll
            for (int i = 0; i < 8; i++) {
                float a = Ps[8 * ty + i][kk];
                aB[i] = pack2(a, a);
            }
            ulonglong2 bb0 = *(const ulonglong2*)&Vs[kk][8 * tx];
            ulonglong2 bb1 = *(const ulonglong2*)&Vs[kk][8 * tx + 4];
            ull b2[4] = {bb0.x, bb0.y, bb1.x, bb1.y};
#pragma unroll
            for (int i = 0; i < 8; i++)
#pragma unroll
                for (int j = 0; j < 4; j++) ffma2(acc2[i][j], aB[i], b2[j]);
        }
    }
#pragma unroll
    for (int i = 0; i < 8; i++) atomicAdd(&s_den[8 * ty + i], dloc[i]);
    __syncthreads();
    {
        size_t rowg = (size_t)bh * Nn + i0 + tid;
        g_dpart[(size_t)part * BH * Nn + rowg] = s_den[tid];
    }
    float* Op = g_Opart + (size_t)part * BH * Nn * HD;
#pragma unroll
    for (int i = 0; i < 8; i++) {
        int il = 8 * ty + i;
        float2 u0 = unpack2(acc2[i][0]);
        float2 u1 = unpack2(acc2[i][1]);
        float2 u2 = unpack2(acc2[i][2]);
        float2 u3 = unpack2(acc2[i][3]);
        float4 v0 = make_float4(u0.x, u0.y, u1.x, u1.y);
        float4 v1 = make_float4(u2.x, u2.y, u3.x, u3.y);
        float* o = &Op[((size_t)bh * Nn + i0 + il) * HD + 8 * tx];
        *(float4*)o = v0;
        *(float4*)(o + 4) = v1;
    }
}

// ---------------------------------------------------------------------------
// Kernel 4b: merge partials -> g_O.  (R10 exact)
// ---------------------------------------------------------------------------
__global__ __launch_bounds__(256) void spv_merge_kernel() {
    int gid = blockIdx.x * 256 + threadIdx.x;
    size_t row = (size_t)gid >> 4;
    int dd = (gid & 15) * 4;
    float den = g_dpart[row] + g_dpart[BH * Nn + row]
              + g_dpart[2 * BH * Nn + row] + g_dpart[3 * BH * Nn + row];
    float inv = 1.f / den;
    size_t base = row * HD + dd;
    float4 s0 = *(const float4*)&g_Opart[base];
    float4 s1 = *(const float4*)&g_Opart[(size_t)BH * Nn * HD + base];
    float4 s2 = *(const float4*)&g_Opart[2 * (size_t)BH * Nn * HD + base];
    float4 s3 = *(const float4*)&g_Opart[3 * (size_t)BH * Nn * HD + base];
    float4 r;
    r.x = (s0.x + s1.x + s2.x + s3.x) * inv;
    r.y = (s0.y + s1.y + s2.y + s3.y) * inv;
    r.z = (s0.z + s1.z + s2.z + s3.z) * inv;
    r.w = (s0.w + s1.w + s2.w + s3.w) * inv;
    *(float4*)&g_O[base] = r;
}

// ---------------------------------------------------------------------------
// Kernel 5: output projection, 64-row tiles (512 blocks).  (R13 exact)
// ---------------------------------------------------------------------------
__global__ __launch_bounds__(128) void outproj_kernel(const float* __restrict__ Wp,
                                                      const float* __restrict__ bp,
                                                      float* __restrict__ out) {
    __shared__ float As[64][33];
    __shared__ float Bs[64][33];
    int tid = threadIdx.x;
    int tx = tid & 7, ty = tid >> 3;      // ty 0..15
    int m0 = blockIdx.y * 64, n0 = blockIdx.x * 64;
    float acc[4][8] = {};
    for (int k0 = 0; k0 < Cc; k0 += 32) {
        int h = k0 >> 6;
#pragma unroll
        for (int l = tid; l < 512; l += 128) {
            int m = l >> 3, c = (l & 7) * 4;
            int mg = m0 + m;
            int bb = mg >> 11, nl = mg & (Nn - 1);
            int d = (k0 + c) & 63;
            float4 v = *(const float4*)&g_O[(((size_t)(bb * Hh + h)) * Nn + nl) * HD + d];
            As[m][c] = v.x; As[m][c + 1] = v.y; As[m][c + 2] = v.z; As[m][c + 3] = v.w;
        }
#pragma unroll
        for (int l = tid; l < 512; l += 128) {
            int n = l >> 3, c = (l & 7) * 4;
            float4 v = *(const float4*)&Wp[(size_t)(n0 + n) * Cc + k0 + c];
            Bs[n][c] = v.x; Bs[n][c + 1] = v.y; Bs[n][c + 2] = v.z; Bs[n][c + 3] = v.w;
        }
        __syncthreads();
#pragma unroll
        for (int kk = 0; kk < 32; kk++) {
            float a[4], b[8];
#pragma unroll
            for (int i = 0; i < 4; i++) a[i] = As[4 * ty + i][kk];
#pragma unroll
            for (int j = 0; j < 8; j++) b[j] = Bs[8 * tx + j][kk];
#pragma unroll
            for (int i = 0; i < 4; i++)
#pragma unroll
                for (int j = 0; j < 8; j++) acc[i][j] += a[i] * b[j];
        }
        __syncthreads();
    }
#pragma unroll
    for (int i = 0; i < 4; i++) {
        int m = m0 + 4 * ty + i;
#pragma unroll
        for (int j = 0; j < 8; j++) {
            int n = n0 + 8 * tx + j;
            out[(size_t)m * Cc + n] = acc[i][j] + bp[n];
        }
    }
}

// ---------------------------------------------------------------------------
extern "C" void kernel_launch(void* const* d_in, const int* in_sizes, int n_in,
                              void* d_out, int out_size) {
    (void)in_sizes; (void)n_in; (void)out_size;
    const float* q   = (const float*)d_in[0];
    const float* k_v = (const float*)d_in[1];
    const float* Wq  = (const float*)d_in[2];
    const float* Wk  = (const float*)d_in[3];
    const float* Wv  = (const float*)d_in[4];
    const float* Wp  = (const float*)d_in[5];
    const float* bp  = (const float*)d_in[6];
    float* out = (float*)d_out;

    dim3 gproj(Cc / 64, (Bb * Nn) / 128, 3);           // (8, 32, 3)
    proj_kernel<<<gproj, 128>>>(q, k_v, Wq, Wk, Wv);

    dim3 gqk(Nn / 64, Nn / 128, BH);                   // (32, 16, 16)
    qk_tc_kernel<<<gqk, 256>>>();

    select_kernel<<<BH * Nn, 256>>>();                 // 32768 paired blocks

    dim3 gspv(Nn / 128, JSPLIT, BH);                   // (16, 4, 16)
    spv_part_kernel<<<gspv, 128>>>();

    spv_merge_kernel<<<(BH * Nn * HD / 4) / 256, 256>>>();

    dim3 gout(Cc / 64, (Bb * Nn) / 64);                // (8, 64) = 512 blocks
    outproj_kernel<<<gout, 128>>>(Wp, bp, out);
}